// round 14
// baseline (speedup 1.0000x reference)
#include <cuda_runtime.h>
#include <math.h>
#include <stdint.h>

#define N_PTS 8192
#define D_FEAT 768

// ---------------- scratch (device globals; no allocs allowed) ----------------
__device__ int   g_fps[2][256];
__device__ float g_zstat[2][2];        // [b][0]=z mean, [b][1]=z var (ddof=1)
__device__ float g_final[2][3][256];   // per-scale scores
__device__ int   g_tok[2][40];         // selected point indices
__device__ float g_hp1[4][80][384];    // mlp layer-1 partial sums (k-split x4)
__device__ float g_hp2[4][80][768];    // mlp layer-2 partial sums (k-split x4)

__device__ __forceinline__ float fmulr(float a, float b){ return __fmul_rn(a,b); }
__device__ __forceinline__ float faddr(float a, float b){ return __fadd_rn(a,b); }

// ---- packed f32x2 helpers — per-lane IEEE RN, bit-identical to scalar RN ops
__device__ __forceinline__ unsigned long long pk2(float lo, float hi){
    unsigned long long r;
    asm("mov.b64 %0, {%1, %2};" : "=l"(r) : "f"(lo), "f"(hi));
    return r;
}
__device__ __forceinline__ void upk2(unsigned long long v, float& lo, float& hi){
    asm("mov.b64 {%0, %1}, %2;" : "=f"(lo), "=f"(hi) : "l"(v));
}
__device__ __forceinline__ unsigned long long add2(unsigned long long a, unsigned long long b){
    unsigned long long r;
    asm("add.rn.f32x2 %0, %1, %2;" : "=l"(r) : "l"(a), "l"(b));
    return r;
}
__device__ __forceinline__ unsigned long long mul2(unsigned long long a, unsigned long long b){
    unsigned long long r;
    asm("mul.rn.f32x2 %0, %1, %2;" : "=l"(r) : "l"(a), "l"(b));
    return r;
}
__device__ __forceinline__ unsigned redux_max_u32(unsigned v){
    unsigned r;
    asm("redux.sync.max.u32 %0, %1, 0xffffffff;" : "=r"(r) : "r"(v));
    return r;
}
__device__ __forceinline__ unsigned redux_min_u32(unsigned v){
    unsigned r;
    asm("redux.sync.min.u32 %0, %1, 0xffffffff;" : "=r"(r) : "r"(v));
    return r;
}

// ---------------- FPS (one block per batch, 1024 thr x 8 pts, 1 bar/iter) ----
// Exact JAX argmax-over-sqrt semantics via hierarchical tie resolution:
//   max_i sqrt_rn(d2_i) = sqrt_rn(max_i d2_i)  (sqrt_rn monotone), and a warp
//   holds global-tie candidates iff sqrt_rn(warp_max) == sqrt_rn(global_max).
// So each warp resolves wl = min{i : sqrt_rn(d2_i)==sqrt_rn(wm)} pre-barrier;
// post-barrier combine: m=max(wm), w = min{wl_w : sqrt_rn(wm_w)==sqrt_rn(m)}.
// Bit-identical selection to the two-phase version; ONE __syncthreads/iter.
__global__ __launch_bounds__(1024) void fps_kernel(const float* __restrict__ coords){
    __shared__ unsigned redw[2][32];   // per-warp max d2 bits (ping-pong)
    __shared__ int      redi[2][32];   // per-warp tie-winner index (ping-pong)
    __shared__ float    redf[32];
    __shared__ float    s_tmp;

    const int b    = blockIdx.x;
    const int tid  = threadIdx.x;
    const int lane = tid & 31;
    const int wid  = tid >> 5;
    const float* cb = coords + (size_t)b * N_PTS * 3;

    // Each thread owns 8 points: j = tid + k*1024 (coords packed in regs).
    unsigned long long px2[4], py2[4], pz2[4];
    float d2[8];
    float zs = 0.f;
    {
        float tx[8], ty[8], tz[8];
        #pragma unroll
        for (int k = 0; k < 8; k++){
            const int j = tid + (k << 10);
            tx[k] = cb[j*3+0];
            ty[k] = cb[j*3+1];
            tz[k] = cb[j*3+2];
            zs += tz[k];
            d2[k] = __int_as_float(0x7f800000);
        }
        #pragma unroll
        for (int k = 0; k < 4; k++){
            px2[k] = pk2(tx[2*k], tx[2*k+1]);
            py2[k] = pk2(ty[2*k], ty[2*k+1]);
            pz2[k] = pk2(tz[2*k], tz[2*k+1]);
        }
    }

    // ---- z mean ----
    for (int o = 16; o; o >>= 1) zs += __shfl_down_sync(0xffffffffu, zs, o);
    if (lane == 0) redf[wid] = zs;
    __syncthreads();
    if (wid == 0){
        float v = redf[lane];
        for (int o = 16; o; o >>= 1) v += __shfl_down_sync(0xffffffffu, v, o);
        if (lane == 0) s_tmp = v;
    }
    __syncthreads();
    const float zmean = s_tmp / (float)N_PTS;
    // ---- z var (ddof=1) ----
    float zd = 0.f;
    #pragma unroll
    for (int k = 0; k < 4; k++){
        float z0, z1; upk2(pz2[k], z0, z1);
        float a = z0 - zmean, c = z1 - zmean;
        zd += a*a + c*c;
    }
    for (int o = 16; o; o >>= 1) zd += __shfl_down_sync(0xffffffffu, zd, o);
    if (lane == 0) redf[wid] = zd;
    __syncthreads();
    if (wid == 0){
        float v = redf[lane];
        for (int o = 16; o; o >>= 1) v += __shfl_down_sync(0xffffffffu, v, o);
        if (lane == 0){
            g_zstat[b][0] = zmean;
            g_zstat[b][1] = v / (float)(N_PTS - 1);
            g_fps[b][0]   = 0;
        }
    }
    __syncthreads();

    int w = 0;
    for (int s = 1; s < 256; s++){
        const int p = s & 1;
        // last-selected coords: L1-resident after the initial full sweep
        const float lx = __ldg(cb + w*3 + 0);
        const float ly = __ldg(cb + w*3 + 1);
        const float lz = __ldg(cb + w*3 + 2);
        const unsigned long long nlx2 = pk2(-lx, -lx);
        const unsigned long long nly2 = pk2(-ly, -ly);
        const unsigned long long nlz2 = pk2(-lz, -lz);

        // packed exact update: (p + (-L)), square-then-sum, RN — matches ref
        float tmax = -1.f;
        #pragma unroll
        for (int k = 0; k < 4; k++){
            unsigned long long dx = add2(px2[k], nlx2);
            unsigned long long dy = add2(py2[k], nly2);
            unsigned long long dz = add2(pz2[k], nlz2);
            unsigned long long sm = add2(add2(mul2(dx,dx), mul2(dy,dy)), mul2(dz,dz));
            float lo, hi; upk2(sm, lo, hi);
            float a = fminf(d2[2*k],   lo);
            float c = fminf(d2[2*k+1], hi);
            d2[2*k]   = a;
            d2[2*k+1] = c;
            tmax = fmaxf(tmax, fmaxf(a, c));
        }

        // ---- warp phase: warp max + warp tie-winner (vs WARP max) ----
        const float wm  = __uint_as_float(redux_max_u32(__float_as_uint(tmax)));
        const float thw = wm - wm * 1e-6f;      // sound superset of sqrt-tie window
        int mi = N_PTS;
        if (tmax >= thw){
            const float srw = __fsqrt_rn(wm);
            #pragma unroll
            for (int k = 0; k < 8; k++){
                if (d2[k] >= thw){
                    if (__fsqrt_rn(d2[k]) == srw){
                        const int idx = tid + (k << 10);
                        if (idx < mi) mi = idx;
                    }
                }
            }
        }
        mi = (int)redux_min_u32((unsigned)mi);
        if (lane == 0){ redw[p][wid] = __float_as_uint(wm); redi[p][wid] = mi; }
        __syncthreads();                                   // the ONLY barrier

        // ---- combine phase (every thread; lanes index the 32 warps) ----
        const unsigned wub = redw[p][lane];
        const int      wii = redi[p][lane];
        const float m    = __uint_as_float(redux_max_u32(wub));
        const float sref = __fsqrt_rn(m);
        const float sw   = __fsqrt_rn(__uint_as_float(wub));
        const int cand   = (sw == sref) ? wii : N_PTS;
        w = (int)redux_min_u32((unsigned)cand);
        if (tid == 0) g_fps[b][s] = w;
        // no d2 zeroing: next iteration dist(w,w)=0 -> fmin absorbs it
    }
}

// ---------------- scoring (8 centers per block, coalesced W1) ----------------
__global__ __launch_bounds__(256) void score_kernel(
    const float* __restrict__ feats, const float* __restrict__ coords,
    const float* __restrict__ gW1, const float* __restrict__ gB1,
    const float* __restrict__ gW2, const float* __restrict__ gB2,
    const float* __restrict__ cW1, const float* __restrict__ cB1,
    const float* __restrict__ cW2, const float* __restrict__ cB2,
    const float* __restrict__ dW1, const float* __restrict__ dB1,
    const float* __restrict__ dW2, const float* __restrict__ dB2){

    __shared__ __align__(16) float feat[8][768];
    __shared__ float hid [8][260];
    __shared__ float sprob[8][16];
    __shared__ float ssaf[8];
    __shared__ int   spidx[8];
    __shared__ int   scnt[8];
    __shared__ float scc[3][8];

    const int blk = blockIdx.x;
    const int b   = blk / 56;
    const int r   = blk % 56;
    int scale, C, S, c0;
    const float *W1, *B1, *W2, *B2;
    if (r < 32){ scale=0; C=256; S=16; c0=r*8;       W1=gW1; B1=gB1; W2=gW2; B2=gB2; }
    else if (r < 48){ scale=1; C=128; S=16; c0=(r-32)*8; W1=cW1; B1=cB1; W2=cW2; B2=cB2; }
    else { scale=2; C=64; S=8; c0=(r-48)*8;          W1=dW1; B1=dB1; W2=dW2; B2=dB2; }

    const int tid  = threadIdx.x;
    const int lane = tid & 31;
    const int wid  = tid >> 5;              // 0..7
    if (tid < 8){ spidx[tid] = g_fps[b][c0 + tid]; scnt[tid] = 0; }
    __syncthreads();

    const float* fb  = feats  + (size_t)b * N_PTS * D_FEAT;
    const float* cbp = coords + (size_t)b * N_PTS * 3;
    #pragma unroll
    for (int g = 0; g < 8; g++){
        const float* src = fb + (size_t)spidx[g] * D_FEAT;
        for (int k = tid; k < 768; k += 256) feat[g][k] = src[k];
    }
    if (tid < 8){
        int p = spidx[tid];
        scc[0][tid] = cbp[p*3+0];
        scc[1][tid] = cbp[p*3+1];
        scc[2][tid] = cbp[p*3+2];
    }
    __syncthreads();

    // hidden = relu(cfeat @ W1^T + b1) — warp-per-row, coalesced weight reads
    {
        const int nrows = C >> 3;
        for (int i = 0; i < nrows; i++){
            const int j = wid + (i << 3);
            const float4* w4 = reinterpret_cast<const float4*>(W1 + (size_t)j * 768);
            float4 wv[6];
            #pragma unroll
            for (int c = 0; c < 6; c++) wv[c] = __ldg(&w4[lane + (c << 5)]);
            float acc[8];
            #pragma unroll
            for (int g = 0; g < 8; g++){
                const float4* f4 = reinterpret_cast<const float4*>(&feat[g][0]);
                float a = 0.f;
                #pragma unroll
                for (int c = 0; c < 6; c++){
                    float4 f = f4[lane + (c << 5)];
                    a += f.x*wv[c].x + f.y*wv[c].y + f.z*wv[c].z + f.w*wv[c].w;
                }
                acc[g] = a;
            }
            #pragma unroll
            for (int g = 0; g < 8; g++)
                for (int o = 16; o; o >>= 1)
                    acc[g] += __shfl_down_sync(0xffffffffu, acc[g], o);
            if (lane == 0){
                const float bb = B1[j];
                #pragma unroll
                for (int g = 0; g < 8; g++) hid[g][j] = fmaxf(acc[g] + bb, 0.f);
            }
        }
    }
    __syncthreads();

    // logits -> sigmoid
    if (tid < 8*S){
        int g = tid / S, s = tid - g*S;
        const float* w2 = W2 + (size_t)s * C;
        float a0 = B2[s], a1 = 0.f, a2 = 0.f, a3 = 0.f;
        for (int j = 0; j < C; j += 4){
            a0 += hid[g][j]   * w2[j];
            a1 += hid[g][j+1] * w2[j+1];
            a2 += hid[g][j+2] * w2[j+2];
            a3 += hid[g][j+3] * w2[j+3];
        }
        float a = (a0 + a1) + (a2 + a3);
        sprob[g][s] = 1.f / (1.f + expf(-a));
    }

    // safety
    if (scale == 0){
        if (tid < 8){
            float t = (scc[2][tid] - g_zstat[b][0]) / 5.0f;
            ssaf[tid] = 1.f + (1.f / (1.f + expf(-t))) * 0.95f;
        }
    } else if (scale == 1){
        if (tid < 8) ssaf[tid] = 1.f + expf(-(g_zstat[b][1] / 0.1f)) * 0.9f;
    } else {
        int cnt[8];
        float cx[8], cy[8], cz[8], aa[8];
        #pragma unroll
        for (int g = 0; g < 8; g++){
            cnt[g] = 0;
            cx[g] = scc[0][g]; cy[g] = scc[1][g]; cz[g] = scc[2][g];
            aa[g] = faddr(faddr(fmulr(cx[g],cx[g]), fmulr(cy[g],cy[g])), fmulr(cz[g],cz[g]));
        }
        for (int j = tid; j < N_PTS; j += 256){
            float bx = cbp[j*3+0], by = cbp[j*3+1], bz = cbp[j*3+2];
            float bb = faddr(faddr(fmulr(bx,bx), fmulr(by,by)), fmulr(bz,bz));
            #pragma unroll
            for (int g = 0; g < 8; g++){
                float dt = faddr(faddr(fmulr(cx[g],bx), fmulr(cy[g],by)), fmulr(cz[g],bz));
                float dd = faddr(faddr(aa[g], bb), -fmulr(2.0f, dt));
                if (fmaxf(dd, 0.f) < 0.25f) cnt[g]++;
            }
        }
        #pragma unroll
        for (int g = 0; g < 8; g++) atomicAdd(&scnt[g], cnt[g]);
    }
    __syncthreads();
    if (scale == 2 && tid < 8)
        ssaf[tid] = 1.f + ((float)scnt[tid] / (float)N_PTS) * 0.95f;
    __syncthreads();

    if (tid < 8){
        float m = 0.f;
        for (int s = 0; s < S; s++) m += sprob[tid][s];
        m /= (float)S;
        g_final[b][scale][c0 + tid] = m * ssaf[tid];
    }
}

// ---------------- stable top-k ----------------
__global__ __launch_bounds__(32) void topk_kernel(){
    const int blk = blockIdx.x;
    const int b = blk / 3, sc = blk % 3;
    const int C   = (sc == 0) ? 256 : (sc == 1 ? 128 : 64);
    const int S   = (sc == 2) ? 8 : 16;
    const int off = (sc == 0) ? 0 : (sc == 1 ? 16 : 32);
    const int lane = threadIdx.x;

    __shared__ float fv[256];
    __shared__ int   taken[256];
    for (int j = lane; j < C; j += 32){ fv[j] = g_final[b][sc][j]; taken[j] = 0; }
    __syncwarp();

    for (int t = 0; t < S; t++){
        float bv = -1e30f; int bi = C;
        for (int j = lane; j < C; j += 32){
            if (!taken[j]){
                float v = fv[j];
                if (v > bv || (v == bv && j < bi)){ bv = v; bi = j; }
            }
        }
        for (int o = 16; o; o >>= 1){
            float ov = __shfl_down_sync(0xffffffffu, bv, o);
            int   oi = __shfl_down_sync(0xffffffffu, bi, o);
            if (ov > bv || (ov == bv && oi < bi)){ bv = ov; bi = oi; }
        }
        bi = __shfl_sync(0xffffffffu, bi, 0);
        if (lane == 0){ taken[bi] = 1; g_tok[b][off + t] = g_fps[b][bi]; }
        __syncwarp();
    }
}

// ---------------- mlp layer 1 (k-split x4, double-buffered) ------------------
// grid (20 token-groups, 3 output-tiles, 4 k-quarters), block 128.
__global__ __launch_bounds__(128) void mlp1_kernel(const float* __restrict__ feats,
    const float* __restrict__ pW1){

    __shared__ __align__(16) float featT[192][4];
    __shared__ float wS[2][128][33];
    __shared__ int stok[4];

    const int tg = blockIdx.x, ot = blockIdx.y, ks = blockIdx.z;
    const int tid = threadIdx.x;

    if (tid < 4){
        int tt = tg*4 + tid;
        int b = tt / 40;
        stok[tid] = b * N_PTS + g_tok[b][tt - b*40];
    }
    __syncthreads();
    #pragma unroll
    for (int t = 0; t < 4; t++){
        const float4* src = reinterpret_cast<const float4*>(
            feats + (size_t)stok[t] * D_FEAT + ks*192);
        for (int i = tid; i < 48; i += 128){
            float4 v = __ldg(&src[i]);
            featT[i*4+0][t] = v.x; featT[i*4+1][t] = v.y;
            featT[i*4+2][t] = v.z; featT[i*4+3][t] = v.w;
        }
    }

    const float* wbase = pW1 + (size_t)(ot*128) * 768 + ks*192;
    const int row = tid >> 3, c4 = tid & 7;
    float4 pf[8];
    #pragma unroll
    for (int j = 0; j < 8; j++){
        int rr = row + j*16;
        pf[j] = __ldg(reinterpret_cast<const float4*>(wbase + (size_t)rr*768) + c4);
    }
    #pragma unroll
    for (int j = 0; j < 8; j++){
        float* d = &wS[0][row + j*16][c4*4];
        d[0] = pf[j].x; d[1] = pf[j].y; d[2] = pf[j].z; d[3] = pf[j].w;
    }
    __syncthreads();

    float a0 = 0.f, a1 = 0.f, a2 = 0.f, a3 = 0.f;
    for (int c = 0; c < 6; c++){
        if (c < 5){
            const float* wb = wbase + (c+1)*32;
            #pragma unroll
            for (int j = 0; j < 8; j++){
                int rr = row + j*16;
                pf[j] = __ldg(reinterpret_cast<const float4*>(wb + (size_t)rr*768) + c4);
            }
        }
        const float* wr = &wS[c & 1][tid][0];
        const int kb = c*32;
        #pragma unroll
        for (int kk = 0; kk < 32; kk++){
            float4 f = *reinterpret_cast<const float4*>(&featT[kb+kk][0]);
            float w = wr[kk];
            a0 += f.x*w; a1 += f.y*w; a2 += f.z*w; a3 += f.w*w;
        }
        if (c < 5){
            #pragma unroll
            for (int j = 0; j < 8; j++){
                float* d = &wS[(c+1) & 1][row + j*16][c4*4];
                d[0] = pf[j].x; d[1] = pf[j].y; d[2] = pf[j].z; d[3] = pf[j].w;
            }
        }
        __syncthreads();
    }
    const int o = ot*128 + tid;
    g_hp1[ks][tg*4+0][o] = a0;
    g_hp1[ks][tg*4+1][o] = a1;
    g_hp1[ks][tg*4+2][o] = a2;
    g_hp1[ks][tg*4+3][o] = a3;
}

// ---------------- mlp layer 2 (k-split x4, double-buffered) ------------------
// grid (20 token-groups, 6 output-tiles, 4 k-quarters), block 128.
__global__ __launch_bounds__(128) void mlp2_kernel(
    const float* __restrict__ pW2, const float* __restrict__ pb1){

    __shared__ __align__(16) float featT[96][4];
    __shared__ float wS[2][128][33];

    const int tg = blockIdx.x, ot = blockIdx.y, ks = blockIdx.z;
    const int tid = threadIdx.x;

    for (int i = tid; i < 384; i += 128){
        int k = i >> 2, t = i & 3;
        int kk = ks*96 + k;
        int row = tg*4 + t;
        featT[k][t] = fmaxf(((g_hp1[0][row][kk] + g_hp1[1][row][kk]) +
                             (g_hp1[2][row][kk] + g_hp1[3][row][kk])) + pb1[kk], 0.f);
    }

    const float* wbase = pW2 + (size_t)(ot*128) * 384 + ks*96;
    const int row = tid >> 3, c4 = tid & 7;
    float4 pf[8];
    #pragma unroll
    for (int j = 0; j < 8; j++){
        int rr = row + j*16;
        pf[j] = __ldg(reinterpret_cast<const float4*>(wbase + (size_t)rr*384) + c4);
    }
    #pragma unroll
    for (int j = 0; j < 8; j++){
        float* d = &wS[0][row + j*16][c4*4];
        d[0] = pf[j].x; d[1] = pf[j].y; d[2] = pf[j].z; d[3] = pf[j].w;
    }
    __syncthreads();

    float a0 = 0.f, a1 = 0.f, a2 = 0.f, a3 = 0.f;
    for (int c = 0; c < 3; c++){
        if (c < 2){
            const float* wb = wbase + (c+1)*32;
            #pragma unroll
            for (int j = 0; j < 8; j++){
                int rr = row + j*16;
                pf[j] = __ldg(reinterpret_cast<const float4*>(wb + (size_t)rr*384) + c4);
            }
        }
        const float* wr = &wS[c & 1][tid][0];
        const int kb = c*32;
        #pragma unroll
        for (int kk = 0; kk < 32; kk++){
            float4 f = *reinterpret_cast<const float4*>(&featT[kb+kk][0]);
            float w = wr[kk];
            a0 += f.x*w; a1 += f.y*w; a2 += f.z*w; a3 += f.w*w;
        }
        if (c < 2){
            #pragma unroll
            for (int j = 0; j < 8; j++){
                float* d = &wS[(c+1) & 1][row + j*16][c4*4];
                d[0] = pf[j].x; d[1] = pf[j].y; d[2] = pf[j].z; d[3] = pf[j].w;
            }
        }
        __syncthreads();
    }
    const int o = ot*128 + tid;
    g_hp2[ks][tg*4+0][o] = a0;
    g_hp2[ks][tg*4+1][o] = a1;
    g_hp2[ks][tg*4+2][o] = a2;
    g_hp2[ks][tg*4+3][o] = a3;
}

// ---------------- LayerNorm (one block per token, combines partials) ---------
__global__ __launch_bounds__(384) void ln_kernel(
    const float* __restrict__ pb2,
    const float* __restrict__ lng, const float* __restrict__ lnb,
    float* __restrict__ out){

    __shared__ float red[32];
    const int t = blockIdx.x;           // 0..79
    const int tid = threadIdx.x, lane = tid & 31, wid = tid >> 5;

    const float v0 = ((g_hp2[0][t][tid]     + g_hp2[1][t][tid]) +
                      (g_hp2[2][t][tid]     + g_hp2[3][t][tid])) + pb2[tid];
    const float v1 = ((g_hp2[0][t][tid+384] + g_hp2[1][t][tid+384]) +
                      (g_hp2[2][t][tid+384] + g_hp2[3][t][tid+384])) + pb2[tid+384];

    float s = v0 + v1;
    for (int o = 16; o; o >>= 1) s += __shfl_down_sync(0xffffffffu, s, o);
    if (lane == 0) red[wid] = s;
    __syncthreads();
    if (tid < 32){
        float v = (tid < 12) ? red[tid] : 0.f;
        for (int o = 16; o; o >>= 1) v += __shfl_down_sync(0xffffffffu, v, o);
        if (tid == 0) red[0] = v;
    }
    __syncthreads();
    const float mu = red[0] * (1.f / 768.f);
    __syncthreads();

    const float d0 = v0 - mu, d1 = v1 - mu;
    float s2 = d0*d0 + d1*d1;
    for (int o = 16; o; o >>= 1) s2 += __shfl_down_sync(0xffffffffu, s2, o);
    if (lane == 0) red[wid] = s2;
    __syncthreads();
    if (tid < 32){
        float v = (tid < 12) ? red[tid] : 0.f;
        for (int o = 16; o; o >>= 1) v += __shfl_down_sync(0xffffffffu, v, o);
        if (tid == 0) red[0] = v;
    }
    __syncthreads();
    const float var = red[0] * (1.f / 768.f);
    const float rs  = rsqrtf(var + 1e-5f);

    float* op = out + (size_t)t * 768;
    op[tid]       = d0 * rs * lng[tid]       + lnb[tid];
    op[tid + 384] = d1 * rs * lng[tid + 384] + lnb[tid + 384];
}

// ---------------- launch ----------------
extern "C" void kernel_launch(void* const* d_in, const int* in_sizes, int n_in,
                              void* d_out, int out_size){
    const float* feats  = (const float*)d_in[0];
    const float* coords = (const float*)d_in[1];
    const float* gW1 = (const float*)d_in[2];
    const float* gB1 = (const float*)d_in[3];
    const float* gW2 = (const float*)d_in[4];
    const float* gB2 = (const float*)d_in[5];
    const float* cW1 = (const float*)d_in[6];
    const float* cB1 = (const float*)d_in[7];
    const float* cW2 = (const float*)d_in[8];
    const float* cB2 = (const float*)d_in[9];
    const float* dW1 = (const float*)d_in[10];
    const float* dB1 = (const float*)d_in[11];
    const float* dW2 = (const float*)d_in[12];
    const float* dB2 = (const float*)d_in[13];
    const float* pW1 = (const float*)d_in[14];
    const float* pb1 = (const float*)d_in[15];
    const float* pW2 = (const float*)d_in[16];
    const float* pb2 = (const float*)d_in[17];
    const float* lng = (const float*)d_in[18];
    const float* lnb = (const float*)d_in[19];
    float* out = (float*)d_out;

    fps_kernel<<<2, 1024>>>(coords);
    score_kernel<<<112, 256>>>(feats, coords,
                               gW1, gB1, gW2, gB2,
                               cW1, cB1, cW2, cB2,
                               dW1, dB1, dW2, dB2);
    topk_kernel<<<6, 32>>>();
    mlp1_kernel<<<dim3(20,3,4), 128>>>(feats, pW1);
    mlp2_kernel<<<dim3(20,6,4), 128>>>(pW2, pb1);
    ln_kernel<<<80, 384>>>(pb2, lng, lnb, out);
}

// round 15
// speedup vs baseline: 1.8233x; 1.8233x over previous
#include <cuda_runtime.h>
#include <math.h>
#include <stdint.h>

#define N_PTS 8192
#define D_FEAT 768

// ---------------- scratch (device globals; no allocs allowed) ----------------
__device__ int   g_fps[2][256];
__device__ float g_zstat[2][2];        // [b][0]=z mean, [b][1]=z var (ddof=1)
__device__ float g_final[2][3][256];   // per-scale scores
__device__ int   g_tok[2][40];         // selected point indices
__device__ float g_hp1[4][80][384];    // mlp layer-1 partial sums (k-split x4)
__device__ float g_hp2[4][80][768];    // mlp layer-2 partial sums (k-split x4)

__device__ __forceinline__ float fmulr(float a, float b){ return __fmul_rn(a,b); }
__device__ __forceinline__ float faddr(float a, float b){ return __fadd_rn(a,b); }

// ---- packed f32x2 helpers — per-lane IEEE RN, bit-identical to scalar RN ops
__device__ __forceinline__ unsigned long long pk2(float lo, float hi){
    unsigned long long r;
    asm("mov.b64 %0, {%1, %2};" : "=l"(r) : "f"(lo), "f"(hi));
    return r;
}
__device__ __forceinline__ void upk2(unsigned long long v, float& lo, float& hi){
    asm("mov.b64 {%0, %1}, %2;" : "=f"(lo), "=f"(hi) : "l"(v));
}
__device__ __forceinline__ unsigned long long add2(unsigned long long a, unsigned long long b){
    unsigned long long r;
    asm("add.rn.f32x2 %0, %1, %2;" : "=l"(r) : "l"(a), "l"(b));
    return r;
}
__device__ __forceinline__ unsigned long long mul2(unsigned long long a, unsigned long long b){
    unsigned long long r;
    asm("mul.rn.f32x2 %0, %1, %2;" : "=l"(r) : "l"(a), "l"(b));
    return r;
}
__device__ __forceinline__ unsigned redux_max_u32(unsigned v){
    unsigned r;
    asm("redux.sync.max.u32 %0, %1, 0xffffffff;" : "=r"(r) : "r"(v));
    return r;
}

// ---------------- FPS (one block per batch, 1024 thr x 8 pts, packed) --------
// Exact JAX argmax-over-sqrt semantics: block max of d2 (monotone under sqrt),
// then min index among points whose __fsqrt_rn(d2) equals __fsqrt_rn(max d2).
// Tie pass is guarded by the GLOBAL threshold, so ~31/32 warps skip it.
__global__ __launch_bounds__(1024) void fps_kernel(const float* __restrict__ coords){
    __shared__ unsigned redw[32];
    __shared__ float redf[32];
    __shared__ float s_tmp;
    __shared__ int   s_win[2];

    const int b    = blockIdx.x;
    const int tid  = threadIdx.x;
    const int lane = tid & 31;
    const int wid  = tid >> 5;
    const float* cb = coords + (size_t)b * N_PTS * 3;

    // Each thread owns 8 points: j = tid + k*1024 (coords packed in regs).
    unsigned long long px2[4], py2[4], pz2[4];
    float d2[8];
    float zs = 0.f;
    {
        float tx[8], ty[8], tz[8];
        #pragma unroll
        for (int k = 0; k < 8; k++){
            const int j = tid + (k << 10);
            tx[k] = cb[j*3+0];
            ty[k] = cb[j*3+1];
            tz[k] = cb[j*3+2];
            zs += tz[k];
            d2[k] = __int_as_float(0x7f800000);
        }
        #pragma unroll
        for (int k = 0; k < 4; k++){
            px2[k] = pk2(tx[2*k], tx[2*k+1]);
            py2[k] = pk2(ty[2*k], ty[2*k+1]);
            pz2[k] = pk2(tz[2*k], tz[2*k+1]);
        }
    }

    // ---- z mean ----
    for (int o = 16; o; o >>= 1) zs += __shfl_down_sync(0xffffffffu, zs, o);
    if (lane == 0) redf[wid] = zs;
    __syncthreads();
    if (wid == 0){
        float v = redf[lane];
        for (int o = 16; o; o >>= 1) v += __shfl_down_sync(0xffffffffu, v, o);
        if (lane == 0) s_tmp = v;
    }
    __syncthreads();
    const float zmean = s_tmp / (float)N_PTS;
    // ---- z var (ddof=1) ----
    float zd = 0.f;
    #pragma unroll
    for (int k = 0; k < 4; k++){
        float z0, z1; upk2(pz2[k], z0, z1);
        float a = z0 - zmean, c = z1 - zmean;
        zd += a*a + c*c;
    }
    for (int o = 16; o; o >>= 1) zd += __shfl_down_sync(0xffffffffu, zd, o);
    if (lane == 0) redf[wid] = zd;
    __syncthreads();
    if (wid == 0){
        float v = redf[lane];
        for (int o = 16; o; o >>= 1) v += __shfl_down_sync(0xffffffffu, v, o);
        if (lane == 0){
            g_zstat[b][0] = zmean;
            g_zstat[b][1] = v / (float)(N_PTS - 1);
            g_fps[b][0]   = 0;
        }
    }
    if (tid < 2) s_win[tid] = N_PTS;
    __syncthreads();

    int w = 0;
    for (int s = 1; s < 256; s++){
        const int p = s & 1;
        // last-selected coords: L1-resident after the initial full sweep
        const float lx = __ldg(cb + w*3 + 0);
        const float ly = __ldg(cb + w*3 + 1);
        const float lz = __ldg(cb + w*3 + 2);
        const unsigned long long nlx2 = pk2(-lx, -lx);
        const unsigned long long nly2 = pk2(-ly, -ly);
        const unsigned long long nlz2 = pk2(-lz, -lz);

        float tmax = -1.f;
        #pragma unroll
        for (int k = 0; k < 4; k++){
            unsigned long long dx = add2(px2[k], nlx2);
            unsigned long long dy = add2(py2[k], nly2);
            unsigned long long dz = add2(pz2[k], nlz2);
            unsigned long long sm = add2(add2(mul2(dx,dx), mul2(dy,dy)), mul2(dz,dz));
            float lo, hi; upk2(sm, lo, hi);
            float a = fminf(d2[2*k],   lo);
            float c = fminf(d2[2*k+1], hi);
            d2[2*k]   = a;
            d2[2*k+1] = c;
            tmax = fmaxf(tmax, fmaxf(a, c));
        }
        // block max: warp redux -> smem -> warp redux (single barrier)
        unsigned wm = redux_max_u32(__float_as_uint(tmax));
        if (lane == 0) redw[wid] = wm;
        __syncthreads();                                    // bar 1
        const float m2 = __uint_as_float(redux_max_u32(redw[lane]));
        if (tid == 0) s_win[1-p] = N_PTS;                   // reset next slot
        const float thr = m2 - m2 * 1e-6f;
        if (tmax >= thr){
            const float sref = __fsqrt_rn(m2);
            #pragma unroll
            for (int k = 0; k < 8; k++){
                if (d2[k] >= thr){
                    if (__fsqrt_rn(d2[k]) == sref) atomicMin(&s_win[p], tid + (k << 10));
                }
            }
        }
        __syncthreads();                                    // bar 2
        w = s_win[p];
        if (tid == 0) g_fps[b][s] = w;
        // no d2 zeroing: next iteration dist(w,w)=0 -> fmin absorbs it
    }
}

// ---------------- scoring (8 centers per block, coalesced W1) ----------------
__global__ __launch_bounds__(256) void score_kernel(
    const float* __restrict__ feats, const float* __restrict__ coords,
    const float* __restrict__ gW1, const float* __restrict__ gB1,
    const float* __restrict__ gW2, const float* __restrict__ gB2,
    const float* __restrict__ cW1, const float* __restrict__ cB1,
    const float* __restrict__ cW2, const float* __restrict__ cB2,
    const float* __restrict__ dW1, const float* __restrict__ dB1,
    const float* __restrict__ dW2, const float* __restrict__ dB2){

    __shared__ __align__(16) float feat[8][768];
    __shared__ float hid [8][260];
    __shared__ float sprob[8][16];
    __shared__ float ssaf[8];
    __shared__ int   spidx[8];
    __shared__ int   scnt[8];
    __shared__ float scc[3][8];

    const int blk = blockIdx.x;
    const int b   = blk / 56;
    const int r   = blk % 56;
    int scale, C, S, c0;
    const float *W1, *B1, *W2, *B2;
    if (r < 32){ scale=0; C=256; S=16; c0=r*8;       W1=gW1; B1=gB1; W2=gW2; B2=gB2; }
    else if (r < 48){ scale=1; C=128; S=16; c0=(r-32)*8; W1=cW1; B1=cB1; W2=cW2; B2=cB2; }
    else { scale=2; C=64; S=8; c0=(r-48)*8;          W1=dW1; B1=dB1; W2=dW2; B2=dB2; }

    const int tid  = threadIdx.x;
    const int lane = tid & 31;
    const int wid  = tid >> 5;              // 0..7
    if (tid < 8){ spidx[tid] = g_fps[b][c0 + tid]; scnt[tid] = 0; }
    __syncthreads();

    const float* fb  = feats  + (size_t)b * N_PTS * D_FEAT;
    const float* cbp = coords + (size_t)b * N_PTS * 3;
    #pragma unroll
    for (int g = 0; g < 8; g++){
        const float* src = fb + (size_t)spidx[g] * D_FEAT;
        for (int k = tid; k < 768; k += 256) feat[g][k] = src[k];
    }
    if (tid < 8){
        int p = spidx[tid];
        scc[0][tid] = cbp[p*3+0];
        scc[1][tid] = cbp[p*3+1];
        scc[2][tid] = cbp[p*3+2];
    }
    __syncthreads();

    // hidden = relu(cfeat @ W1^T + b1) — warp-per-row, coalesced weight reads
    {
        const int nrows = C >> 3;
        for (int i = 0; i < nrows; i++){
            const int j = wid + (i << 3);
            const float4* w4 = reinterpret_cast<const float4*>(W1 + (size_t)j * 768);
            float4 wv[6];
            #pragma unroll
            for (int c = 0; c < 6; c++) wv[c] = __ldg(&w4[lane + (c << 5)]);
            float acc[8];
            #pragma unroll
            for (int g = 0; g < 8; g++){
                const float4* f4 = reinterpret_cast<const float4*>(&feat[g][0]);
                float a = 0.f;
                #pragma unroll
                for (int c = 0; c < 6; c++){
                    float4 f = f4[lane + (c << 5)];
                    a += f.x*wv[c].x + f.y*wv[c].y + f.z*wv[c].z + f.w*wv[c].w;
                }
                acc[g] = a;
            }
            #pragma unroll
            for (int g = 0; g < 8; g++)
                for (int o = 16; o; o >>= 1)
                    acc[g] += __shfl_down_sync(0xffffffffu, acc[g], o);
            if (lane == 0){
                const float bb = B1[j];
                #pragma unroll
                for (int g = 0; g < 8; g++) hid[g][j] = fmaxf(acc[g] + bb, 0.f);
            }
        }
    }
    __syncthreads();

    // logits -> sigmoid
    if (tid < 8*S){
        int g = tid / S, s = tid - g*S;
        const float* w2 = W2 + (size_t)s * C;
        float a0 = B2[s], a1 = 0.f, a2 = 0.f, a3 = 0.f;
        for (int j = 0; j < C; j += 4){
            a0 += hid[g][j]   * w2[j];
            a1 += hid[g][j+1] * w2[j+1];
            a2 += hid[g][j+2] * w2[j+2];
            a3 += hid[g][j+3] * w2[j+3];
        }
        float a = (a0 + a1) + (a2 + a3);
        sprob[g][s] = 1.f / (1.f + expf(-a));
    }

    // safety
    if (scale == 0){
        if (tid < 8){
            float t = (scc[2][tid] - g_zstat[b][0]) / 5.0f;
            ssaf[tid] = 1.f + (1.f / (1.f + expf(-t))) * 0.95f;
        }
    } else if (scale == 1){
        if (tid < 8) ssaf[tid] = 1.f + expf(-(g_zstat[b][1] / 0.1f)) * 0.9f;
    } else {
        int cnt[8];
        float cx[8], cy[8], cz[8], aa[8];
        #pragma unroll
        for (int g = 0; g < 8; g++){
            cnt[g] = 0;
            cx[g] = scc[0][g]; cy[g] = scc[1][g]; cz[g] = scc[2][g];
            aa[g] = faddr(faddr(fmulr(cx[g],cx[g]), fmulr(cy[g],cy[g])), fmulr(cz[g],cz[g]));
        }
        for (int j = tid; j < N_PTS; j += 256){
            float bx = cbp[j*3+0], by = cbp[j*3+1], bz = cbp[j*3+2];
            float bb = faddr(faddr(fmulr(bx,bx), fmulr(by,by)), fmulr(bz,bz));
            #pragma unroll
            for (int g = 0; g < 8; g++){
                float dt = faddr(faddr(fmulr(cx[g],bx), fmulr(cy[g],by)), fmulr(cz[g],bz));
                float dd = faddr(faddr(aa[g], bb), -fmulr(2.0f, dt));
                if (fmaxf(dd, 0.f) < 0.25f) cnt[g]++;
            }
        }
        #pragma unroll
        for (int g = 0; g < 8; g++) atomicAdd(&scnt[g], cnt[g]);
    }
    __syncthreads();
    if (scale == 2 && tid < 8)
        ssaf[tid] = 1.f + ((float)scnt[tid] / (float)N_PTS) * 0.95f;
    __syncthreads();

    if (tid < 8){
        float m = 0.f;
        for (int s = 0; s < S; s++) m += sprob[tid][s];
        m /= (float)S;
        g_final[b][scale][c0 + tid] = m * ssaf[tid];
    }
}

// ---------------- stable top-k ----------------
__global__ __launch_bounds__(32) void topk_kernel(){
    const int blk = blockIdx.x;
    const int b = blk / 3, sc = blk % 3;
    const int C   = (sc == 0) ? 256 : (sc == 1 ? 128 : 64);
    const int S   = (sc == 2) ? 8 : 16;
    const int off = (sc == 0) ? 0 : (sc == 1 ? 16 : 32);
    const int lane = threadIdx.x;

    __shared__ float fv[256];
    __shared__ int   taken[256];
    for (int j = lane; j < C; j += 32){ fv[j] = g_final[b][sc][j]; taken[j] = 0; }
    __syncwarp();

    for (int t = 0; t < S; t++){
        float bv = -1e30f; int bi = C;
        for (int j = lane; j < C; j += 32){
            if (!taken[j]){
                float v = fv[j];
                if (v > bv || (v == bv && j < bi)){ bv = v; bi = j; }
            }
        }
        for (int o = 16; o; o >>= 1){
            float ov = __shfl_down_sync(0xffffffffu, bv, o);
            int   oi = __shfl_down_sync(0xffffffffu, bi, o);
            if (ov > bv || (ov == bv && oi < bi)){ bv = ov; bi = oi; }
        }
        bi = __shfl_sync(0xffffffffu, bi, 0);
        if (lane == 0){ taken[bi] = 1; g_tok[b][off + t] = g_fps[b][bi]; }
        __syncwarp();
    }
}

// ---------------- mlp layer 1 (k-split x4, double-buffered) ------------------
// grid (20 token-groups, 3 output-tiles, 4 k-quarters), block 128.
__global__ __launch_bounds__(128) void mlp1_kernel(const float* __restrict__ feats,
    const float* __restrict__ pW1){

    __shared__ __align__(16) float featT[192][4];
    __shared__ float wS[2][128][33];
    __shared__ int stok[4];

    const int tg = blockIdx.x, ot = blockIdx.y, ks = blockIdx.z;
    const int tid = threadIdx.x;

    if (tid < 4){
        int tt = tg*4 + tid;
        int b = tt / 40;
        stok[tid] = b * N_PTS + g_tok[b][tt - b*40];
    }
    __syncthreads();
    #pragma unroll
    for (int t = 0; t < 4; t++){
        const float4* src = reinterpret_cast<const float4*>(
            feats + (size_t)stok[t] * D_FEAT + ks*192);
        for (int i = tid; i < 48; i += 128){
            float4 v = __ldg(&src[i]);
            featT[i*4+0][t] = v.x; featT[i*4+1][t] = v.y;
            featT[i*4+2][t] = v.z; featT[i*4+3][t] = v.w;
        }
    }

    const float* wbase = pW1 + (size_t)(ot*128) * 768 + ks*192;
    const int row = tid >> 3, c4 = tid & 7;
    float4 pf[8];
    #pragma unroll
    for (int j = 0; j < 8; j++){
        int rr = row + j*16;
        pf[j] = __ldg(reinterpret_cast<const float4*>(wbase + (size_t)rr*768) + c4);
    }
    #pragma unroll
    for (int j = 0; j < 8; j++){
        float* d = &wS[0][row + j*16][c4*4];
        d[0] = pf[j].x; d[1] = pf[j].y; d[2] = pf[j].z; d[3] = pf[j].w;
    }
    __syncthreads();

    float a0 = 0.f, a1 = 0.f, a2 = 0.f, a3 = 0.f;
    for (int c = 0; c < 6; c++){
        if (c < 5){
            const float* wb = wbase + (c+1)*32;
            #pragma unroll
            for (int j = 0; j < 8; j++){
                int rr = row + j*16;
                pf[j] = __ldg(reinterpret_cast<const float4*>(wb + (size_t)rr*768) + c4);
            }
        }
        const float* wr = &wS[c & 1][tid][0];
        const int kb = c*32;
        #pragma unroll
        for (int kk = 0; kk < 32; kk++){
            float4 f = *reinterpret_cast<const float4*>(&featT[kb+kk][0]);
            float w = wr[kk];
            a0 += f.x*w; a1 += f.y*w; a2 += f.z*w; a3 += f.w*w;
        }
        if (c < 5){
            #pragma unroll
            for (int j = 0; j < 8; j++){
                float* d = &wS[(c+1) & 1][row + j*16][c4*4];
                d[0] = pf[j].x; d[1] = pf[j].y; d[2] = pf[j].z; d[3] = pf[j].w;
            }
        }
        __syncthreads();
    }
    const int o = ot*128 + tid;
    g_hp1[ks][tg*4+0][o] = a0;
    g_hp1[ks][tg*4+1][o] = a1;
    g_hp1[ks][tg*4+2][o] = a2;
    g_hp1[ks][tg*4+3][o] = a3;
}

// ---------------- mlp layer 2 (k-split x4, double-buffered) ------------------
// grid (20 token-groups, 6 output-tiles, 4 k-quarters), block 128.
__global__ __launch_bounds__(128) void mlp2_kernel(
    const float* __restrict__ pW2, const float* __restrict__ pb1){

    __shared__ __align__(16) float featT[96][4];
    __shared__ float wS[2][128][33];

    const int tg = blockIdx.x, ot = blockIdx.y, ks = blockIdx.z;
    const int tid = threadIdx.x;

    for (int i = tid; i < 384; i += 128){
        int k = i >> 2, t = i & 3;
        int kk = ks*96 + k;
        int row = tg*4 + t;
        featT[k][t] = fmaxf(((g_hp1[0][row][kk] + g_hp1[1][row][kk]) +
                             (g_hp1[2][row][kk] + g_hp1[3][row][kk])) + pb1[kk], 0.f);
    }

    const float* wbase = pW2 + (size_t)(ot*128) * 384 + ks*96;
    const int row = tid >> 3, c4 = tid & 7;
    float4 pf[8];
    #pragma unroll
    for (int j = 0; j < 8; j++){
        int rr = row + j*16;
        pf[j] = __ldg(reinterpret_cast<const float4*>(wbase + (size_t)rr*384) + c4);
    }
    #pragma unroll
    for (int j = 0; j < 8; j++){
        float* d = &wS[0][row + j*16][c4*4];
        d[0] = pf[j].x; d[1] = pf[j].y; d[2] = pf[j].z; d[3] = pf[j].w;
    }
    __syncthreads();

    float a0 = 0.f, a1 = 0.f, a2 = 0.f, a3 = 0.f;
    for (int c = 0; c < 3; c++){
        if (c < 2){
            const float* wb = wbase + (c+1)*32;
            #pragma unroll
            for (int j = 0; j < 8; j++){
                int rr = row + j*16;
                pf[j] = __ldg(reinterpret_cast<const float4*>(wb + (size_t)rr*384) + c4);
            }
        }
        const float* wr = &wS[c & 1][tid][0];
        const int kb = c*32;
        #pragma unroll
        for (int kk = 0; kk < 32; kk++){
            float4 f = *reinterpret_cast<const float4*>(&featT[kb+kk][0]);
            float w = wr[kk];
            a0 += f.x*w; a1 += f.y*w; a2 += f.z*w; a3 += f.w*w;
        }
        if (c < 2){
            #pragma unroll
            for (int j = 0; j < 8; j++){
                float* d = &wS[(c+1) & 1][row + j*16][c4*4];
                d[0] = pf[j].x; d[1] = pf[j].y; d[2] = pf[j].z; d[3] = pf[j].w;
            }
        }
        __syncthreads();
    }
    const int o = ot*128 + tid;
    g_hp2[ks][tg*4+0][o] = a0;
    g_hp2[ks][tg*4+1][o] = a1;
    g_hp2[ks][tg*4+2][o] = a2;
    g_hp2[ks][tg*4+3][o] = a3;
}

// ---------------- LayerNorm (one block per token, combines partials) ---------
__global__ __launch_bounds__(384) void ln_kernel(
    const float* __restrict__ pb2,
    const float* __restrict__ lng, const float* __restrict__ lnb,
    float* __restrict__ out){

    __shared__ float red[32];
    const int t = blockIdx.x;           // 0..79
    const int tid = threadIdx.x, lane = tid & 31, wid = tid >> 5;

    const float v0 = ((g_hp2[0][t][tid]     + g_hp2[1][t][tid]) +
                      (g_hp2[2][t][tid]     + g_hp2[3][t][tid])) + pb2[tid];
    const float v1 = ((g_hp2[0][t][tid+384] + g_hp2[1][t][tid+384]) +
                      (g_hp2[2][t][tid+384] + g_hp2[3][t][tid+384])) + pb2[tid+384];

    float s = v0 + v1;
    for (int o = 16; o; o >>= 1) s += __shfl_down_sync(0xffffffffu, s, o);
    if (lane == 0) red[wid] = s;
    __syncthreads();
    if (tid < 32){
        float v = (tid < 12) ? red[tid] : 0.f;
        for (int o = 16; o; o >>= 1) v += __shfl_down_sync(0xffffffffu, v, o);
        if (tid == 0) red[0] = v;
    }
    __syncthreads();
    const float mu = red[0] * (1.f / 768.f);
    __syncthreads();

    const float d0 = v0 - mu, d1 = v1 - mu;
    float s2 = d0*d0 + d1*d1;
    for (int o = 16; o; o >>= 1) s2 += __shfl_down_sync(0xffffffffu, s2, o);
    if (lane == 0) red[wid] = s2;
    __syncthreads();
    if (tid < 32){
        float v = (tid < 12) ? red[tid] : 0.f;
        for (int o = 16; o; o >>= 1) v += __shfl_down_sync(0xffffffffu, v, o);
        if (tid == 0) red[0] = v;
    }
    __syncthreads();
    const float var = red[0] * (1.f / 768.f);
    const float rs  = rsqrtf(var + 1e-5f);

    float* op = out + (size_t)t * 768;
    op[tid]       = d0 * rs * lng[tid]       + lnb[tid];
    op[tid + 384] = d1 * rs * lng[tid + 384] + lnb[tid + 384];
}

// ---------------- launch ----------------
extern "C" void kernel_launch(void* const* d_in, const int* in_sizes, int n_in,
                              void* d_out, int out_size){
    const float* feats  = (const float*)d_in[0];
    const float* coords = (const float*)d_in[1];
    const float* gW1 = (const float*)d_in[2];
    const float* gB1 = (const float*)d_in[3];
    const float* gW2 = (const float*)d_in[4];
    const float* gB2 = (const float*)d_in[5];
    const float* cW1 = (const float*)d_in[6];
    const float* cB1 = (const float*)d_in[7];
    const float* cW2 = (const float*)d_in[8];
    const float* cB2 = (const float*)d_in[9];
    const float* dW1 = (const float*)d_in[10];
    const float* dB1 = (const float*)d_in[11];
    const float* dW2 = (const float*)d_in[12];
    const float* dB2 = (const float*)d_in[13];
    const float* pW1 = (const float*)d_in[14];
    const float* pb1 = (const float*)d_in[15];
    const float* pW2 = (const float*)d_in[16];
    const float* pb2 = (const float*)d_in[17];
    const float* lng = (const float*)d_in[18];
    const float* lnb = (const float*)d_in[19];
    float* out = (float*)d_out;

    fps_kernel<<<2, 1024>>>(coords);
    score_kernel<<<112, 256>>>(feats, coords,
                               gW1, gB1, gW2, gB2,
                               cW1, cB1, cW2, cB2,
                               dW1, dB1, dW2, dB2);
    topk_kernel<<<6, 32>>>();
    mlp1_kernel<<<dim3(20,3,4), 128>>>(feats, pW1);
    mlp2_kernel<<<dim3(20,6,4), 128>>>(pW2, pb1);
    ln_kernel<<<80, 384>>>(pb2, lng, lnb, out);
}

// round 17
// speedup vs baseline: 1.8664x; 1.0236x over previous
#include <cuda_runtime.h>
#include <math.h>
#include <stdint.h>

#define N_PTS 8192
#define D_FEAT 768

// ---------------- scratch (device globals; no allocs allowed) ----------------
__device__ int   g_fps[2][256];
__device__ float g_zstat[2][2];        // [b][0]=z mean, [b][1]=z var (ddof=1)
__device__ float g_final[2][3][256];   // per-scale scores
__device__ int   g_tok[2][40];         // selected point indices
__device__ float g_hp1[4][80][384];    // mlp layer-1 partial sums (k-split x4)
__device__ float g_hp2[4][80][768];    // mlp layer-2 partial sums (k-split x4)

__device__ __forceinline__ float fmulr(float a, float b){ return __fmul_rn(a,b); }
__device__ __forceinline__ float faddr(float a, float b){ return __fadd_rn(a,b); }

// ---- packed f32x2 helpers — per-lane IEEE RN, bit-identical to scalar RN ops
__device__ __forceinline__ unsigned long long pk2(float lo, float hi){
    unsigned long long r;
    asm("mov.b64 %0, {%1, %2};" : "=l"(r) : "f"(lo), "f"(hi));
    return r;
}
__device__ __forceinline__ void upk2(unsigned long long v, float& lo, float& hi){
    asm("mov.b64 {%0, %1}, %2;" : "=f"(lo), "=f"(hi) : "l"(v));
}
__device__ __forceinline__ unsigned long long add2(unsigned long long a, unsigned long long b){
    unsigned long long r;
    asm("add.rn.f32x2 %0, %1, %2;" : "=l"(r) : "l"(a), "l"(b));
    return r;
}
__device__ __forceinline__ unsigned long long mul2(unsigned long long a, unsigned long long b){
    unsigned long long r;
    asm("mul.rn.f32x2 %0, %1, %2;" : "=l"(r) : "l"(a), "l"(b));
    return r;
}
__device__ __forceinline__ unsigned redux_max_u32(unsigned v){
    unsigned r;
    asm("redux.sync.max.u32 %0, %1, 0xffffffff;" : "=r"(r) : "r"(v));
    return r;
}

// ---------------- FPS (one block per batch, 1024 thr x 8 pts, packed) --------
// Exact JAX argmax-over-sqrt semantics: block max of d2 (monotone under sqrt),
// then min index among points whose __fsqrt_rn(d2) equals __fsqrt_rn(max d2).
// Tie pass is guarded by the GLOBAL threshold, so ~31/32 warps skip it.
__global__ __launch_bounds__(1024) void fps_kernel(const float* __restrict__ coords){
    __shared__ unsigned redw[32];
    __shared__ float redf[32];
    __shared__ float s_tmp;
    __shared__ int   s_win[2];

    const int b    = blockIdx.x;
    const int tid  = threadIdx.x;
    const int lane = tid & 31;
    const int wid  = tid >> 5;
    const float* cb = coords + (size_t)b * N_PTS * 3;

    // Each thread owns 8 points: j = tid + k*1024 (coords packed in regs).
    unsigned long long px2[4], py2[4], pz2[4];
    float d2[8];
    float zs = 0.f;
    {
        float tx[8], ty[8], tz[8];
        #pragma unroll
        for (int k = 0; k < 8; k++){
            const int j = tid + (k << 10);
            tx[k] = cb[j*3+0];
            ty[k] = cb[j*3+1];
            tz[k] = cb[j*3+2];
            zs += tz[k];
            d2[k] = __int_as_float(0x7f800000);
        }
        #pragma unroll
        for (int k = 0; k < 4; k++){
            px2[k] = pk2(tx[2*k], tx[2*k+1]);
            py2[k] = pk2(ty[2*k], ty[2*k+1]);
            pz2[k] = pk2(tz[2*k], tz[2*k+1]);
        }
    }

    // ---- z mean ----
    for (int o = 16; o; o >>= 1) zs += __shfl_down_sync(0xffffffffu, zs, o);
    if (lane == 0) redf[wid] = zs;
    __syncthreads();
    if (wid == 0){
        float v = redf[lane];
        for (int o = 16; o; o >>= 1) v += __shfl_down_sync(0xffffffffu, v, o);
        if (lane == 0) s_tmp = v;
    }
    __syncthreads();
    const float zmean = s_tmp / (float)N_PTS;
    // ---- z var (ddof=1) ----
    float zd = 0.f;
    #pragma unroll
    for (int k = 0; k < 4; k++){
        float z0, z1; upk2(pz2[k], z0, z1);
        float a = z0 - zmean, c = z1 - zmean;
        zd += a*a + c*c;
    }
    for (int o = 16; o; o >>= 1) zd += __shfl_down_sync(0xffffffffu, zd, o);
    if (lane == 0) redf[wid] = zd;
    __syncthreads();
    if (wid == 0){
        float v = redf[lane];
        for (int o = 16; o; o >>= 1) v += __shfl_down_sync(0xffffffffu, v, o);
        if (lane == 0){
            g_zstat[b][0] = zmean;
            g_zstat[b][1] = v / (float)(N_PTS - 1);
            g_fps[b][0]   = 0;
        }
    }
    if (tid < 2) s_win[tid] = N_PTS;
    __syncthreads();

    int w = 0;
    for (int s = 1; s < 256; s++){
        const int p = s & 1;
        // last-selected coords: L1-resident after the initial full sweep
        const float lx = __ldg(cb + w*3 + 0);
        const float ly = __ldg(cb + w*3 + 1);
        const float lz = __ldg(cb + w*3 + 2);
        const unsigned long long nlx2 = pk2(-lx, -lx);
        const unsigned long long nly2 = pk2(-ly, -ly);
        const unsigned long long nlz2 = pk2(-lz, -lz);

        float tmax = -1.f;
        #pragma unroll
        for (int k = 0; k < 4; k++){
            unsigned long long dx = add2(px2[k], nlx2);
            unsigned long long dy = add2(py2[k], nly2);
            unsigned long long dz = add2(pz2[k], nlz2);
            unsigned long long sm = add2(add2(mul2(dx,dx), mul2(dy,dy)), mul2(dz,dz));
            float lo, hi; upk2(sm, lo, hi);
            float a = fminf(d2[2*k],   lo);
            float c = fminf(d2[2*k+1], hi);
            d2[2*k]   = a;
            d2[2*k+1] = c;
            tmax = fmaxf(tmax, fmaxf(a, c));
        }
        // block max: warp redux -> smem -> warp redux (single barrier)
        unsigned wm = redux_max_u32(__float_as_uint(tmax));
        if (lane == 0) redw[wid] = wm;
        __syncthreads();                                    // bar 1
        const float m2 = __uint_as_float(redux_max_u32(redw[lane]));
        if (tid == 0) s_win[1-p] = N_PTS;                   // reset next slot
        const float thr = m2 - m2 * 1e-6f;
        if (tmax >= thr){
            const float sref = __fsqrt_rn(m2);
            #pragma unroll
            for (int k = 0; k < 8; k++){
                if (d2[k] >= thr){
                    if (__fsqrt_rn(d2[k]) == sref) atomicMin(&s_win[p], tid + (k << 10));
                }
            }
        }
        __syncthreads();                                    // bar 2
        w = s_win[p];
        if (tid == 0) g_fps[b][s] = w;
        // no d2 zeroing: next iteration dist(w,w)=0 -> fmin absorbs it
    }
}

// ---------------- scoring (8 centers per block, 512 thr, warp-per-row) -------
__global__ __launch_bounds__(512) void score_kernel(
    const float* __restrict__ feats, const float* __restrict__ coords,
    const float* __restrict__ gW1, const float* __restrict__ gB1,
    const float* __restrict__ gW2, const float* __restrict__ gB2,
    const float* __restrict__ cW1, const float* __restrict__ cB1,
    const float* __restrict__ cW2, const float* __restrict__ cB2,
    const float* __restrict__ dW1, const float* __restrict__ dB1,
    const float* __restrict__ dW2, const float* __restrict__ dB2){

    __shared__ __align__(16) float feat[8][768];
    __shared__ float hid [8][260];
    __shared__ float sprob[8][16];
    __shared__ float ssaf[8];
    __shared__ int   spidx[8];
    __shared__ int   scnt[8];
    __shared__ float scc[3][8];

    const int blk = blockIdx.x;
    const int b   = blk / 56;
    const int r   = blk % 56;
    int scale, C, S, c0;
    const float *W1, *B1, *W2, *B2;
    if (r < 32){ scale=0; C=256; S=16; c0=r*8;       W1=gW1; B1=gB1; W2=gW2; B2=gB2; }
    else if (r < 48){ scale=1; C=128; S=16; c0=(r-32)*8; W1=cW1; B1=cB1; W2=cW2; B2=cB2; }
    else { scale=2; C=64; S=8; c0=(r-48)*8;          W1=dW1; B1=dB1; W2=dW2; B2=dB2; }

    const int tid  = threadIdx.x;
    const int lane = tid & 31;
    const int wid  = tid >> 5;              // 0..15
    if (tid < 8){ spidx[tid] = g_fps[b][c0 + tid]; scnt[tid] = 0; }
    __syncthreads();

    const float* fb  = feats  + (size_t)b * N_PTS * D_FEAT;
    const float* cbp = coords + (size_t)b * N_PTS * 3;
    #pragma unroll
    for (int g = 0; g < 8; g++){
        const float* src = fb + (size_t)spidx[g] * D_FEAT;
        for (int k = tid; k < 768; k += 512) feat[g][k] = src[k];
    }
    if (tid < 8){
        int p = spidx[tid];
        scc[0][tid] = cbp[p*3+0];
        scc[1][tid] = cbp[p*3+1];
        scc[2][tid] = cbp[p*3+2];
    }
    __syncthreads();

    // hidden = relu(cfeat @ W1^T + b1) — warp-per-row over 16 warps
    {
        const int nrows = C >> 4;           // rows per warp
        for (int i = 0; i < nrows; i++){
            const int j = wid + (i << 4);
            const float4* w4 = reinterpret_cast<const float4*>(W1 + (size_t)j * 768);
            float4 wv[6];
            #pragma unroll
            for (int c = 0; c < 6; c++) wv[c] = __ldg(&w4[lane + (c << 5)]);
            float acc[8];
            #pragma unroll
            for (int g = 0; g < 8; g++){
                const float4* f4 = reinterpret_cast<const float4*>(&feat[g][0]);
                float a = 0.f;
                #pragma unroll
                for (int c = 0; c < 6; c++){
                    float4 f = f4[lane + (c << 5)];
                    a += f.x*wv[c].x + f.y*wv[c].y + f.z*wv[c].z + f.w*wv[c].w;
                }
                acc[g] = a;
            }
            #pragma unroll
            for (int g = 0; g < 8; g++)
                for (int o = 16; o; o >>= 1)
                    acc[g] += __shfl_down_sync(0xffffffffu, acc[g], o);
            if (lane == 0){
                const float bb = B1[j];
                #pragma unroll
                for (int g = 0; g < 8; g++) hid[g][j] = fmaxf(acc[g] + bb, 0.f);
            }
        }
    }
    __syncthreads();

    // logits -> sigmoid
    if (tid < 8*S){
        int g = tid / S, s = tid - g*S;
        const float* w2 = W2 + (size_t)s * C;
        float a0 = B2[s], a1 = 0.f, a2 = 0.f, a3 = 0.f;
        for (int j = 0; j < C; j += 4){
            a0 += hid[g][j]   * w2[j];
            a1 += hid[g][j+1] * w2[j+1];
            a2 += hid[g][j+2] * w2[j+2];
            a3 += hid[g][j+3] * w2[j+3];
        }
        float a = (a0 + a1) + (a2 + a3);
        sprob[g][s] = 1.f / (1.f + expf(-a));
    }

    // safety
    if (scale == 0){
        if (tid < 8){
            float t = (scc[2][tid] - g_zstat[b][0]) / 5.0f;
            ssaf[tid] = 1.f + (1.f / (1.f + expf(-t))) * 0.95f;
        }
    } else if (scale == 1){
        if (tid < 8) ssaf[tid] = 1.f + expf(-(g_zstat[b][1] / 0.1f)) * 0.9f;
    } else {
        int cnt[8];
        float cx[8], cy[8], cz[8], aa[8];
        #pragma unroll
        for (int g = 0; g < 8; g++){
            cnt[g] = 0;
            cx[g] = scc[0][g]; cy[g] = scc[1][g]; cz[g] = scc[2][g];
            aa[g] = faddr(faddr(fmulr(cx[g],cx[g]), fmulr(cy[g],cy[g])), fmulr(cz[g],cz[g]));
        }
        for (int j = tid; j < N_PTS; j += 512){
            float bx = cbp[j*3+0], by = cbp[j*3+1], bz = cbp[j*3+2];
            float bb = faddr(faddr(fmulr(bx,bx), fmulr(by,by)), fmulr(bz,bz));
            #pragma unroll
            for (int g = 0; g < 8; g++){
                float dt = faddr(faddr(fmulr(cx[g],bx), fmulr(cy[g],by)), fmulr(cz[g],bz));
                float dd = faddr(faddr(aa[g], bb), -fmulr(2.0f, dt));
                if (fmaxf(dd, 0.f) < 0.25f) cnt[g]++;
            }
        }
        #pragma unroll
        for (int g = 0; g < 8; g++) atomicAdd(&scnt[g], cnt[g]);
    }
    __syncthreads();
    if (scale == 2 && tid < 8)
        ssaf[tid] = 1.f + ((float)scnt[tid] / (float)N_PTS) * 0.95f;
    __syncthreads();

    if (tid < 8){
        float m = 0.f;
        for (int s = 0; s < S; s++) m += sprob[tid][s];
        m /= (float)S;
        g_final[b][scale][c0 + tid] = m * ssaf[tid];
    }
}

// ---------------- stable top-k ----------------
__global__ __launch_bounds__(32) void topk_kernel(){
    const int blk = blockIdx.x;
    const int b = blk / 3, sc = blk % 3;
    const int C   = (sc == 0) ? 256 : (sc == 1 ? 128 : 64);
    const int S   = (sc == 2) ? 8 : 16;
    const int off = (sc == 0) ? 0 : (sc == 1 ? 16 : 32);
    const int lane = threadIdx.x;

    __shared__ float fv[256];
    __shared__ int   taken[256];
    for (int j = lane; j < C; j += 32){ fv[j] = g_final[b][sc][j]; taken[j] = 0; }
    __syncwarp();

    for (int t = 0; t < S; t++){
        float bv = -1e30f; int bi = C;
        for (int j = lane; j < C; j += 32){
            if (!taken[j]){
                float v = fv[j];
                if (v > bv || (v == bv && j < bi)){ bv = v; bi = j; }
            }
        }
        for (int o = 16; o; o >>= 1){
            float ov = __shfl_down_sync(0xffffffffu, bv, o);
            int   oi = __shfl_down_sync(0xffffffffu, bi, o);
            if (ov > bv || (ov == bv && oi < bi)){ bv = ov; bi = oi; }
        }
        bi = __shfl_sync(0xffffffffu, bi, 0);
        if (lane == 0){ taken[bi] = 1; g_tok[b][off + t] = g_fps[b][bi]; }
        __syncwarp();
    }
}

// ---------------- mlp layer 1 (k-split x4, double-buffered) ------------------
// grid (20 token-groups, 3 output-tiles, 4 k-quarters), block 128.
__global__ __launch_bounds__(128) void mlp1_kernel(const float* __restrict__ feats,
    const float* __restrict__ pW1){

    __shared__ __align__(16) float featT[192][4];
    __shared__ float wS[2][128][33];
    __shared__ int stok[4];

    const int tg = blockIdx.x, ot = blockIdx.y, ks = blockIdx.z;
    const int tid = threadIdx.x;

    if (tid < 4){
        int tt = tg*4 + tid;
        int b = tt / 40;
        stok[tid] = b * N_PTS + g_tok[b][tt - b*40];
    }
    __syncthreads();
    #pragma unroll
    for (int t = 0; t < 4; t++){
        const float4* src = reinterpret_cast<const float4*>(
            feats + (size_t)stok[t] * D_FEAT + ks*192);
        for (int i = tid; i < 48; i += 128){
            float4 v = __ldg(&src[i]);
            featT[i*4+0][t] = v.x; featT[i*4+1][t] = v.y;
            featT[i*4+2][t] = v.z; featT[i*4+3][t] = v.w;
        }
    }

    const float* wbase = pW1 + (size_t)(ot*128) * 768 + ks*192;
    const int row = tid >> 3, c4 = tid & 7;
    float4 pf[8];
    #pragma unroll
    for (int j = 0; j < 8; j++){
        int rr = row + j*16;
        pf[j] = __ldg(reinterpret_cast<const float4*>(wbase + (size_t)rr*768) + c4);
    }
    #pragma unroll
    for (int j = 0; j < 8; j++){
        float* d = &wS[0][row + j*16][c4*4];
        d[0] = pf[j].x; d[1] = pf[j].y; d[2] = pf[j].z; d[3] = pf[j].w;
    }
    __syncthreads();

    float a0 = 0.f, a1 = 0.f, a2 = 0.f, a3 = 0.f;
    for (int c = 0; c < 6; c++){
        if (c < 5){
            const float* wb = wbase + (c+1)*32;
            #pragma unroll
            for (int j = 0; j < 8; j++){
                int rr = row + j*16;
                pf[j] = __ldg(reinterpret_cast<const float4*>(wb + (size_t)rr*768) + c4);
            }
        }
        const float* wr = &wS[c & 1][tid][0];
        const int kb = c*32;
        #pragma unroll
        for (int kk = 0; kk < 32; kk++){
            float4 f = *reinterpret_cast<const float4*>(&featT[kb+kk][0]);
            float w = wr[kk];
            a0 += f.x*w; a1 += f.y*w; a2 += f.z*w; a3 += f.w*w;
        }
        if (c < 5){
            #pragma unroll
            for (int j = 0; j < 8; j++){
                float* d = &wS[(c+1) & 1][row + j*16][c4*4];
                d[0] = pf[j].x; d[1] = pf[j].y; d[2] = pf[j].z; d[3] = pf[j].w;
            }
        }
        __syncthreads();
    }
    const int o = ot*128 + tid;
    g_hp1[ks][tg*4+0][o] = a0;
    g_hp1[ks][tg*4+1][o] = a1;
    g_hp1[ks][tg*4+2][o] = a2;
    g_hp1[ks][tg*4+3][o] = a3;
}

// ---------------- mlp layer 2 (k-split x4, double-buffered) ------------------
// grid (20 token-groups, 6 output-tiles, 4 k-quarters), block 128.
__global__ __launch_bounds__(128) void mlp2_kernel(
    const float* __restrict__ pW2, const float* __restrict__ pb1){

    __shared__ __align__(16) float featT[96][4];
    __shared__ float wS[2][128][33];

    const int tg = blockIdx.x, ot = blockIdx.y, ks = blockIdx.z;
    const int tid = threadIdx.x;

    for (int i = tid; i < 384; i += 128){
        int k = i >> 2, t = i & 3;
        int kk = ks*96 + k;
        int row = tg*4 + t;
        featT[k][t] = fmaxf(((g_hp1[0][row][kk] + g_hp1[1][row][kk]) +
                             (g_hp1[2][row][kk] + g_hp1[3][row][kk])) + pb1[kk], 0.f);
    }

    const float* wbase = pW2 + (size_t)(ot*128) * 384 + ks*96;
    const int row = tid >> 3, c4 = tid & 7;
    float4 pf[8];
    #pragma unroll
    for (int j = 0; j < 8; j++){
        int rr = row + j*16;
        pf[j] = __ldg(reinterpret_cast<const float4*>(wbase + (size_t)rr*384) + c4);
    }
    #pragma unroll
    for (int j = 0; j < 8; j++){
        float* d = &wS[0][row + j*16][c4*4];
        d[0] = pf[j].x; d[1] = pf[j].y; d[2] = pf[j].z; d[3] = pf[j].w;
    }
    __syncthreads();

    float a0 = 0.f, a1 = 0.f, a2 = 0.f, a3 = 0.f;
    for (int c = 0; c < 3; c++){
        if (c < 2){
            const float* wb = wbase + (c+1)*32;
            #pragma unroll
            for (int j = 0; j < 8; j++){
                int rr = row + j*16;
                pf[j] = __ldg(reinterpret_cast<const float4*>(wb + (size_t)rr*384) + c4);
            }
        }
        const float* wr = &wS[c & 1][tid][0];
        const int kb = c*32;
        #pragma unroll
        for (int kk = 0; kk < 32; kk++){
            float4 f = *reinterpret_cast<const float4*>(&featT[kb+kk][0]);
            float w = wr[kk];
            a0 += f.x*w; a1 += f.y*w; a2 += f.z*w; a3 += f.w*w;
        }
        if (c < 2){
            #pragma unroll
            for (int j = 0; j < 8; j++){
                float* d = &wS[(c+1) & 1][row + j*16][c4*4];
                d[0] = pf[j].x; d[1] = pf[j].y; d[2] = pf[j].z; d[3] = pf[j].w;
            }
        }
        __syncthreads();
    }
    const int o = ot*128 + tid;
    g_hp2[ks][tg*4+0][o] = a0;
    g_hp2[ks][tg*4+1][o] = a1;
    g_hp2[ks][tg*4+2][o] = a2;
    g_hp2[ks][tg*4+3][o] = a3;
}

// ---------------- LayerNorm (one block per token, combines partials) ---------
__global__ __launch_bounds__(384) void ln_kernel(
    const float* __restrict__ pb2,
    const float* __restrict__ lng, const float* __restrict__ lnb,
    float* __restrict__ out){

    __shared__ float red[32];
    const int t = blockIdx.x;           // 0..79
    const int tid = threadIdx.x, lane = tid & 31, wid = tid >> 5;

    const float v0 = ((g_hp2[0][t][tid]     + g_hp2[1][t][tid]) +
                      (g_hp2[2][t][tid]     + g_hp2[3][t][tid])) + pb2[tid];
    const float v1 = ((g_hp2[0][t][tid+384] + g_hp2[1][t][tid+384]) +
                      (g_hp2[2][t][tid+384] + g_hp2[3][t][tid+384])) + pb2[tid+384];

    float s = v0 + v1;
    for (int o = 16; o; o >>= 1) s += __shfl_down_sync(0xffffffffu, s, o);
    if (lane == 0) red[wid] = s;
    __syncthreads();
    if (tid < 32){
        float v = (tid < 12) ? red[tid] : 0.f;
        for (int o = 16; o; o >>= 1) v += __shfl_down_sync(0xffffffffu, v, o);
        if (tid == 0) red[0] = v;
    }
    __syncthreads();
    const float mu = red[0] * (1.f / 768.f);
    __syncthreads();

    const float d0 = v0 - mu, d1 = v1 - mu;
    float s2 = d0*d0 + d1*d1;
    for (int o = 16; o; o >>= 1) s2 += __shfl_down_sync(0xffffffffu, s2, o);
    if (lane == 0) red[wid] = s2;
    __syncthreads();
    if (tid < 32){
        float v = (tid < 12) ? red[tid] : 0.f;
        for (int o = 16; o; o >>= 1) v += __shfl_down_sync(0xffffffffu, v, o);
        if (tid == 0) red[0] = v;
    }
    __syncthreads();
    const float var = red[0] * (1.f / 768.f);
    const float rs  = rsqrtf(var + 1e-5f);

    float* op = out + (size_t)t * 768;
    op[tid]       = d0 * rs * lng[tid]       + lnb[tid];
    op[tid + 384] = d1 * rs * lng[tid + 384] + lnb[tid + 384];
}

// ---------------- launch ----------------
extern "C" void kernel_launch(void* const* d_in, const int* in_sizes, int n_in,
                              void* d_out, int out_size){
    const float* feats  = (const float*)d_in[0];
    const float* coords = (const float*)d_in[1];
    const float* gW1 = (const float*)d_in[2];
    const float* gB1 = (const float*)d_in[3];
    const float* gW2 = (const float*)d_in[4];
    const float* gB2 = (const float*)d_in[5];
    const float* cW1 = (const float*)d_in[6];
    const float* cB1 = (const float*)d_in[7];
    const float* cW2 = (const float*)d_in[8];
    const float* cB2 = (const float*)d_in[9];
    const float* dW1 = (const float*)d_in[10];
    const float* dB1 = (const float*)d_in[11];
    const float* dW2 = (const float*)d_in[12];
    const float* dB2 = (const float*)d_in[13];
    const float* pW1 = (const float*)d_in[14];
    const float* pb1 = (const float*)d_in[15];
    const float* pW2 = (const float*)d_in[16];
    const float* pb2 = (const float*)d_in[17];
    const float* lng = (const float*)d_in[18];
    const float* lnb = (const float*)d_in[19];
    float* out = (float*)d_out;

    fps_kernel<<<2, 1024>>>(coords);
    score_kernel<<<112, 512>>>(feats, coords,
                               gW1, gB1, gW2, gB2,
                               cW1, cB1, cW2, cB2,
                               dW1, dB1, dW2, dB2);
    topk_kernel<<<6, 32>>>();
    mlp1_kernel<<<dim3(20,3,4), 128>>>(feats, pW1);
    mlp2_kernel<<<dim3(20,6,4), 128>>>(pW2, pb1);
    ln_kernel<<<80, 384>>>(pb2, lng, lnb, out);
}